// round 5
// baseline (speedup 1.0000x reference)
#include <cuda_runtime.h>

#define DDEPTH 8
#define HDIM   4096
#define NT     256
#define NWARP  (NT / 32)     // 8
#define HPT    16            // hidden dims per thread (256*16 = 4096)
#define EPSV   1e-6f

// One CTA per (s,b) site, 256 threads, 16 h/thread, online softmax over depth.
// q*w staged in smem (re-read per depth) to keep regs under the 3-CTA/SM cap.
__global__ __launch_bounds__(NT, 3)
void fullattnres_kernel(const float* __restrict__ values,
                        const float* __restrict__ query,
                        const float* __restrict__ weight,
                        float* __restrict__ out,
                        int SB)
{
    __shared__ float sqw[HDIM];            // 16 KiB: fused q*w
    __shared__ float red[2][2 * NWARP];    // parity-buffered reduction scratch

    const int tid  = threadIdx.x;
    const int lane = tid & 31;
    const int warp = tid >> 5;
    const int h    = tid * HPT;

    const size_t base = (size_t)blockIdx.x * HDIM + h;
    const size_t dstr = (size_t)SB * HDIM;
    const float* p    = values + base;

    // Stage fused q*w into smem (one pass; q/w are L2-resident)
    #pragma unroll
    for (int i = 0; i < HPT; i += 4) {
        const float4 q = *(const float4*)(query + h + i);
        const float4 w = *(const float4*)(weight + h + i);
        *(float4*)(sqw + h + i) = make_float4(q.x*w.x, q.y*w.y, q.z*w.z, q.w*w.w);
    }
    __syncthreads();

    // Preload depth 0
    float4 va[4];
    #pragma unroll
    for (int i = 0; i < 4; i++)
        va[i] = *(const float4*)(p + i * 4);

    float  m = -3.402823466e38f;
    float  s = 0.f;
    float4 acc[4];
    #pragma unroll
    for (int i = 0; i < 4; i++) acc[i] = make_float4(0.f, 0.f, 0.f, 0.f);

    #pragma unroll
    for (int d = 0; d < DDEPTH; d++) {
        // partials for current depth; qw re-read from smem (short-lived temps)
        float ss = 0.f, dp = 0.f;
        #pragma unroll
        for (int i = 0; i < 4; i++) {
            const float4 v  = va[i];
            const float4 qw = *(const float4*)(sqw + h + i * 4);
            ss += v.x*v.x + v.y*v.y + v.z*v.z + v.w*v.w;
            dp += qw.x*v.x + qw.y*v.y + qw.z*v.z + qw.w*v.w;
        }

        // prefetch next depth before the reduce barrier
        float4 vb[4];
        if (d < DDEPTH - 1) {
            const float* pn = p + (size_t)(d + 1) * dstr;
            #pragma unroll
            for (int i = 0; i < 4; i++)
                vb[i] = *(const float4*)(pn + i * 4);
        }

        // warp butterfly reduce (2 scalars)
        #pragma unroll
        for (int off = 16; off > 0; off >>= 1) {
            ss += __shfl_xor_sync(0xFFFFFFFFu, ss, off);
            dp += __shfl_xor_sync(0xFFFFFFFFu, dp, off);
        }
        if (lane == 0) {
            red[d & 1][warp]         = ss;
            red[d & 1][NWARP + warp] = dp;
        }
        __syncthreads();   // single barrier per depth; parity buffer avoids WAR

        // cross-warp: every thread scans the 8 warp partials (broadcast LDS)
        float sst = 0.f, dpt = 0.f;
        #pragma unroll
        for (int w2 = 0; w2 < NWARP; w2++) {
            sst += red[d & 1][w2];
            dpt += red[d & 1][NWARP + w2];
        }
        const float l = dpt * rsqrtf(sst * (1.0f / HDIM) + EPSV);

        // online softmax update
        const float mn = fmaxf(m, l);
        const float cs = __expf(m - mn);   // d==0: exp(-inf)=0, acc is zero
        const float e  = __expf(l - mn);
        s = s * cs + e;
        #pragma unroll
        for (int i = 0; i < 4; i++) {
            acc[i].x = acc[i].x * cs + e * va[i].x;
            acc[i].y = acc[i].y * cs + e * va[i].y;
            acc[i].z = acc[i].z * cs + e * va[i].z;
            acc[i].w = acc[i].w * cs + e * va[i].w;
            va[i] = vb[i];
        }
        m = mn;
    }

    const float inv = 1.0f / s;
    #pragma unroll
    for (int i = 0; i < 4; i++) {
        float4 o = make_float4(acc[i].x * inv, acc[i].y * inv,
                               acc[i].z * inv, acc[i].w * inv);
        *(float4*)(out + base + i * 4) = o;
    }
}

extern "C" void kernel_launch(void* const* d_in, const int* in_sizes, int n_in,
                              void* d_out, int out_size)
{
    const float* values = (const float*)d_in[0];  // [D,S,B,H]
    const float* query  = (const float*)d_in[1];  // [H]
    const float* weight = (const float*)d_in[2];  // [H]
    float* out = (float*)d_out;                   // [S,B,H]

    const int H  = in_sizes[1];                   // 4096
    const int SB = out_size / H;                  // S*B = 4096

    fullattnres_kernel<<<SB, NT>>>(values, query, weight, out, SB);
}

// round 7
// speedup vs baseline: 1.2575x; 1.2575x over previous
#include <cuda_runtime.h>
#include <cstdint>

#define DDEPTH 8
#define HDIM   4096
#define HALF   (HDIM / 2)   // 2048 per CTA
#define NT     256
#define NWARP  (NT / 32)    // 8
#define HPT    8            // hidden dims per thread (256*8 = 2048)
#define EPSV   1e-6f

__device__ __forceinline__ uint32_t smem_u32(const void* p) {
    uint32_t a;
    asm("{ .reg .u64 t; cvta.to.shared.u64 t, %1; cvt.u32.u64 %0, t; }"
        : "=r"(a) : "l"(p));
    return a;
}

// 2-CTA cluster per (s,b) site; each CTA owns half of H. All 8 depths held in
// registers; single reduction; 16-float partial-sum exchange over DSMEM with
// per-thread cluster-scope release arrives (16 producers -> count=16 barrier).
__global__ __launch_bounds__(NT, 2) __cluster_dims__(2, 1, 1)
void fullattnres_kernel(const float* __restrict__ values,
                        const float* __restrict__ query,
                        const float* __restrict__ weight,
                        float* __restrict__ out,
                        int SB)
{
    __shared__ float red[NWARP][16];   // per-warp partials
    __shared__ float fin[16];          // this CTA's half-sums [0..7]=ss [8..15]=dp
    __shared__ float mbox[16];         // peer CTA's half-sums (written remotely)
    __shared__ unsigned long long mbar;

    const int tid  = threadIdx.x;
    const int lane = tid & 31;
    const int warp = tid >> 5;
    const unsigned rank = blockIdx.x & 1;      // cluster rank (cluster_dims x=2)
    const unsigned peer = rank ^ 1u;
    const int site = blockIdx.x >> 1;
    const int h    = (int)rank * HALF + tid * HPT;

    const uint32_t mb_a   = smem_u32(&mbar);
    const uint32_t mbox_a = smem_u32(mbox);

    // init mbarrier: 16 arrivals expected (one per peer reducer thread)
    if (tid == 0)
        asm volatile("mbarrier.init.shared.b64 [%0], %1;" :: "r"(mb_a), "r"(16) : "memory");
    __syncthreads();
    // non-blocking cluster arrive: matching wait deferred until the exchange,
    // so the load burst overlaps cluster startup skew.
    asm volatile("barrier.cluster.arrive.aligned;" ::: "memory");

    // ── Load ALL depths up front: 16 independent LDG.128 per thread ──
    const size_t base = (size_t)site * HDIM + h;
    const size_t dstr = (size_t)SB * HDIM;
    const float* p    = values + base;

    float4 va[DDEPTH], vb[DDEPTH];
    #pragma unroll
    for (int d = 0; d < DDEPTH; d++) {
        const float* pd = p + (size_t)d * dstr;
        va[d] = *(const float4*)(pd);
        vb[d] = *(const float4*)(pd + 4);
    }

    // fused q*w for this thread's 8 dims (L2-resident)
    const float4 q0 = *(const float4*)(query + h);
    const float4 q1 = *(const float4*)(query + h + 4);
    const float4 w0 = *(const float4*)(weight + h);
    const float4 w1 = *(const float4*)(weight + h + 4);
    const float4 qw0 = make_float4(q0.x*w0.x, q0.y*w0.y, q0.z*w0.z, q0.w*w0.w);
    const float4 qw1 = make_float4(q1.x*w1.x, q1.y*w1.y, q1.z*w1.z, q1.w*w1.w);

    // per-thread partials for all depths
    float ss[DDEPTH], dp[DDEPTH];
    #pragma unroll
    for (int d = 0; d < DDEPTH; d++) {
        ss[d] = va[d].x*va[d].x + va[d].y*va[d].y + va[d].z*va[d].z + va[d].w*va[d].w
              + vb[d].x*vb[d].x + vb[d].y*vb[d].y + vb[d].z*vb[d].z + vb[d].w*vb[d].w;
        dp[d] = qw0.x*va[d].x + qw0.y*va[d].y + qw0.z*va[d].z + qw0.w*va[d].w
              + qw1.x*vb[d].x + qw1.y*vb[d].y + qw1.z*vb[d].z + qw1.w*vb[d].w;
    }

    // ── single warp butterfly over 16 scalars (once per CTA lifetime) ──
    #pragma unroll
    for (int off = 16; off > 0; off >>= 1) {
        #pragma unroll
        for (int d = 0; d < DDEPTH; d++) {
            ss[d] += __shfl_xor_sync(0xFFFFFFFFu, ss[d], off);
            dp[d] += __shfl_xor_sync(0xFFFFFFFFu, dp[d], off);
        }
    }
    if (lane == 0) {
        #pragma unroll
        for (int d = 0; d < DDEPTH; d++) {
            red[warp][d]     = ss[d];
            red[warp][8 + d] = dp[d];
        }
    }
    __syncthreads();

    // cross-warp: 16 threads each own one scalar (8 adds)
    if (tid < 16) {
        float s = 0.f;
        #pragma unroll
        for (int w2 = 0; w2 < NWARP; w2++) s += red[w2][tid];
        fin[tid] = s;
    }
    __syncthreads();

    // ── DSMEM exchange of the 16 half-sums with the peer CTA ──
    asm volatile("barrier.cluster.wait.aligned;" ::: "memory");  // peer mbar ready
    if (tid < 16) {
        const float v = fin[tid];
        uint32_t ra_box, ra_bar;
        asm volatile("mapa.shared::cluster.u32 %0, %1, %2;"
                     : "=r"(ra_box) : "r"(mbox_a + tid * 4), "r"(peer));
        asm volatile("st.shared::cluster.f32 [%0], %1;"
                     :: "r"(ra_box), "f"(v) : "memory");
        asm volatile("mapa.shared::cluster.u32 %0, %1, %2;"
                     : "=r"(ra_bar) : "r"(mb_a), "r"(peer));
        // cluster-scope RELEASE arrive: orders this thread's remote store
        // before the peer's acquire-wait observes the arrival.
        asm volatile("mbarrier.arrive.release.cluster.shared::cluster.b64 _, [%0];"
                     :: "r"(ra_bar) : "memory");
    }
    // wait for all 16 peer scalars (parity 0, cluster-scope acquire)
    {
        uint32_t done;
        asm volatile(
            "{ .reg .pred p;"
            "  mbarrier.try_wait.parity.acquire.cluster.shared::cta.b64 p, [%1], %2;"
            "  selp.b32 %0, 1, 0, p; }"
            : "=r"(done) : "r"(mb_a), "r"(0u) : "memory");
        if (!done) {
            asm volatile(
                "{ .reg .pred P1;"
                "WAIT_LOOP_%=:"
                "  mbarrier.try_wait.parity.acquire.cluster.shared::cta.b64 P1, [%0], %1, 0x989680;"
                "  @P1 bra.uni WAIT_DONE_%=;"
                "  bra.uni WAIT_LOOP_%=;"
                "WAIT_DONE_%=: }"
                :: "r"(mb_a), "r"(0u) : "memory");
        }
    }

    // ── softmax over depth (redundant per thread; broadcast LDS) ──
    float wt[DDEPTH];
    float mx = -3.402823466e38f;
    #pragma unroll
    for (int d = 0; d < DDEPTH; d++) {
        const float sst   = fin[d]     + mbox[d];
        const float dpt   = fin[8 + d] + mbox[8 + d];
        const float logit = dpt * rsqrtf(sst * (1.0f / HDIM) + EPSV);
        wt[d] = logit;
        mx = fmaxf(mx, logit);
    }
    float sum = 0.f;
    #pragma unroll
    for (int d = 0; d < DDEPTH; d++) {
        wt[d] = __expf(wt[d] - mx);
        sum += wt[d];
    }
    const float inv = 1.0f / sum;

    // ── combine straight from registers ──
    float4 o0 = make_float4(0.f, 0.f, 0.f, 0.f);
    float4 o1 = make_float4(0.f, 0.f, 0.f, 0.f);
    #pragma unroll
    for (int d = 0; d < DDEPTH; d++) {
        const float wd = wt[d] * inv;
        o0.x += wd * va[d].x;  o0.y += wd * va[d].y;
        o0.z += wd * va[d].z;  o0.w += wd * va[d].w;
        o1.x += wd * vb[d].x;  o1.y += wd * vb[d].y;
        o1.z += wd * vb[d].z;  o1.w += wd * vb[d].w;
    }
    *(float4*)(out + base)     = o0;
    *(float4*)(out + base + 4) = o1;

    // no CTA exits while a peer's remote ops could still be in flight
    asm volatile("barrier.cluster.arrive.aligned;" ::: "memory");
    asm volatile("barrier.cluster.wait.aligned;" ::: "memory");
}

extern "C" void kernel_launch(void* const* d_in, const int* in_sizes, int n_in,
                              void* d_out, int out_size)
{
    const float* values = (const float*)d_in[0];  // [D,S,B,H]
    const float* query  = (const float*)d_in[1];  // [H]
    const float* weight = (const float*)d_in[2];  // [H]
    float* out = (float*)d_out;                   // [S,B,H]

    const int H  = in_sizes[1];                   // 4096
    const int SB = out_size / H;                  // S*B = 4096

    fullattnres_kernel<<<SB * 2, NT>>>(values, query, weight, out, SB);
}